// round 13
// baseline (speedup 1.0000x reference)
#include <cuda_runtime.h>

#define D_MODEL 1024
#define N_TOK   2048
#define BSZ     2
#define TOKENS  (BSZ * N_TOK)      // 4096
#define NHEAD   16
#define DH      64
#define INV_TEMPER 0.125f          // 1/sqrt(64)

typedef unsigned long long ull;

// ---- packed f32x2 helpers (sm_103a FFMA2 path; ptxas won't auto-fuse) ----
__device__ __forceinline__ ull pk2(float lo, float hi) {
    ull r;
    asm("mov.b64 %0, {%1, %2};" : "=l"(r)
        : "r"(__float_as_uint(lo)), "r"(__float_as_uint(hi)));
    return r;
}
__device__ __forceinline__ void upk2(float& lo, float& hi, ull v) {
    unsigned int a, b;
    asm("mov.b64 {%0, %1}, %2;" : "=r"(a), "=r"(b) : "l"(v));
    lo = __uint_as_float(a); hi = __uint_as_float(b);
}
__device__ __forceinline__ ull fma2(ull a, ull b, ull c) {
    ull d;
    asm("fma.rn.f32x2 %0, %1, %2, %3;" : "=l"(d) : "l"(a), "l"(b), "l"(c));
    return d;
}
__device__ __forceinline__ ull mul2(ull a, ull b) {
    ull d;
    asm("mul.rn.f32x2 %0, %1, %2;" : "=l"(d) : "l"(a), "l"(b));
    return d;
}
// direct register-pair reinterpret (zero-MOV: LDS.128 result is an aligned quad)
__device__ __forceinline__ ull rp2(const float& f) {
    return *reinterpret_cast<const ull*>(&f);
}

// -------- scratch (static device globals; no allocation allowed) --------
__device__ float g_h[TOKENS * D_MODEL];
__device__ float g_qp[TOKENS * D_MODEL];
__device__ float g_kp[TOKENS * D_MODEL];
__device__ float g_vp[TOKENS * D_MODEL];
__device__ float g_o[TOKENS * D_MODEL];

// ======================= LayerNorm =======================
__global__ __launch_bounds__(256) void ln_kernel(const float* __restrict__ x,
                          const float* __restrict__ gamma,
                          const float* __restrict__ beta) {
    int t = blockIdx.x;
    const float* row = x + (size_t)t * D_MODEL;
    float* out = g_h + (size_t)t * D_MODEL;
    int tid = threadIdx.x;

    float4 v = reinterpret_cast<const float4*>(row)[tid];
    float s  = v.x + v.y + v.z + v.w;
    float ss = v.x * v.x + v.y * v.y + v.z * v.z + v.w * v.w;

    #pragma unroll
    for (int o = 16; o > 0; o >>= 1) {
        s  += __shfl_xor_sync(0xffffffffu, s,  o);
        ss += __shfl_xor_sync(0xffffffffu, ss, o);
    }
    __shared__ float rs[8], rss[8];
    __shared__ float mu_s, rstd_s;
    int w = tid >> 5, l = tid & 31;
    if (l == 0) { rs[w] = s; rss[w] = ss; }
    __syncthreads();
    if (tid == 0) {
        float S = 0.f, SS = 0.f;
        #pragma unroll
        for (int i = 0; i < 8; i++) { S += rs[i]; SS += rss[i]; }
        float mu  = S * (1.0f / D_MODEL);
        float var = SS * (1.0f / D_MODEL) - mu * mu;
        mu_s = mu;
        rstd_s = rsqrtf(var + 1e-5f);
    }
    __syncthreads();
    float mu = mu_s, rstd = rstd_s;

    float4 g = reinterpret_cast<const float4*>(gamma)[tid];
    float4 b = reinterpret_cast<const float4*>(beta)[tid];
    float4 o;
    o.x = (v.x - mu) * rstd * g.x + b.x;
    o.y = (v.y - mu) * rstd * g.y + b.y;
    o.z = (v.z - mu) * rstd * g.z + b.z;
    o.w = (v.w - mu) * rstd * g.w + b.w;
    reinterpret_cast<float4*>(out)[tid] = o;
}

// ============ shared GEMM core: 128x64x16 tile, FFMA2 swapped-pair scheme ============
// accA[p][q] = (C[r0][c0], C[r1][c1]); accB[p][q] = (C[r0][c1], C[r1][c0])
// where r0 = ty*8 + 2p, r1 = r0+1, c0 = tx*4 + 2q, c1 = c0+1.
__device__ __forceinline__ void gemm_core(const float* __restrict__ A,
                                          const float* __restrict__ B,
                                          int bm, int bn, int tid,
                                          float As[2][16][132], float Bs[2][16][64],
                                          ull accA[4][2], ull accB[4][2]) {
    const int Kdim = 1024, Ndim = 1024;
    const int NKT = Kdim / 16;      // 64 k-tiles
    int ty = tid >> 4, tx = tid & 15;

    int ar = tid >> 1, acg = (tid & 1) << 3;           // A: row, col-group(8)
    int brr = tid >> 4, bcc = (tid & 15) << 2;         // B: row, col-group(4)
    const float* Ap = A + (size_t)(bm + ar) * Kdim + acg;
    const float* Bp = B + (size_t)brr * Ndim + bn + bcc;

    #pragma unroll
    for (int p = 0; p < 4; p++)
        #pragma unroll
        for (int q = 0; q < 2; q++) { accA[p][q] = 0ull; accB[p][q] = 0ull; }

    // prologue: k-tile 0 -> buffer 0
    {
        float4 a0 = *reinterpret_cast<const float4*>(Ap);
        float4 a1 = *reinterpret_cast<const float4*>(Ap + 4);
        As[0][acg + 0][ar] = a0.x; As[0][acg + 1][ar] = a0.y;
        As[0][acg + 2][ar] = a0.z; As[0][acg + 3][ar] = a0.w;
        As[0][acg + 4][ar] = a1.x; As[0][acg + 5][ar] = a1.y;
        As[0][acg + 6][ar] = a1.z; As[0][acg + 7][ar] = a1.w;
        float4 b4 = *reinterpret_cast<const float4*>(Bp);
        *reinterpret_cast<float4*>(&Bs[0][brr][bcc]) = b4;
    }
    Ap += 16;                       // pointer-bump addressing (fewer live regs)
    Bp += 16 * Ndim;
    __syncthreads();

    for (int kt = 0; kt < NKT; kt++) {
        int cur = kt & 1;
        float4 pa0, pa1, pb;
        if (kt < NKT - 1) {
            pa0 = *reinterpret_cast<const float4*>(Ap);
            pa1 = *reinterpret_cast<const float4*>(Ap + 4);
            pb  = *reinterpret_cast<const float4*>(Bp);
            Ap += 16;
            Bp += 16 * Ndim;
        }
        #pragma unroll
        for (int kk = 0; kk < 16; kk++) {
            float4 af0 = *reinterpret_cast<const float4*>(&As[cur][kk][ty * 8]);
            float4 af1 = *reinterpret_cast<const float4*>(&As[cur][kk][ty * 8 + 4]);
            ull a[4];
            a[0] = rp2(af0.x);
            a[1] = rp2(af0.z);
            a[2] = rp2(af1.x);
            a[3] = rp2(af1.z);
            float4 b4 = *reinterpret_cast<float4*>(&Bs[cur][kk][tx * 4]);
            ull b01 = rp2(b4.x), b23 = rp2(b4.z);               // direct pairs: zero-MOV
            ull b10 = pk2(b4.y, b4.x), b32 = pk2(b4.w, b4.z);   // swapped pairs
            #pragma unroll
            for (int p = 0; p < 4; p++) {
                accA[p][0] = fma2(a[p], b01, accA[p][0]);
                accB[p][0] = fma2(a[p], b10, accB[p][0]);
                accA[p][1] = fma2(a[p], b23, accA[p][1]);
                accB[p][1] = fma2(a[p], b32, accB[p][1]);
            }
        }
        if (kt < NKT - 1) {
            int nxt = cur ^ 1;
            As[nxt][acg + 0][ar] = pa0.x; As[nxt][acg + 1][ar] = pa0.y;
            As[nxt][acg + 2][ar] = pa0.z; As[nxt][acg + 3][ar] = pa0.w;
            As[nxt][acg + 4][ar] = pa1.x; As[nxt][acg + 5][ar] = pa1.y;
            As[nxt][acg + 6][ar] = pa1.z; As[nxt][acg + 7][ar] = pa1.w;
            *reinterpret_cast<float4*>(&Bs[nxt][brr][bcc]) = pb;
        }
        __syncthreads();
    }
}

// unpack the mixed-label accumulators of one row-pair into two row vectors of 4 cols
__device__ __forceinline__ void unswap_rows(const ull accA[2], const ull accB[2],
                                            float lo[4], float hi[4]) {
    float a0l, a0h, b0l, b0h, a1l, a1h, b1l, b1h;
    upk2(a0l, a0h, accA[0]);   // (r0c0, r1c1)
    upk2(b0l, b0h, accB[0]);   // (r0c1, r1c0)
    upk2(a1l, a1h, accA[1]);   // (r0c2, r1c3)
    upk2(b1l, b1h, accB[1]);   // (r0c3, r1c2)
    lo[0] = a0l; lo[1] = b0l; lo[2] = a1l; lo[3] = b1l;   // row r0
    hi[0] = b0h; hi[1] = a0h; hi[2] = b1h; hi[3] = a1h;   // row r1
}

// ======================= fused Q/K/V projection GEMM (one launch, 3 outputs) ============
// __launch_bounds__(256,4): cap regs at 64 -> 4 CTAs/SM -> fewer/fuller waves.
__global__ __launch_bounds__(256, 4) void qkv_gemm(const float* __restrict__ Wq,
                                                const float* __restrict__ bq,
                                                const float* __restrict__ Wk,
                                                const float* __restrict__ bk,
                                                const float* __restrict__ Wv,
                                                const float* __restrict__ bv) {
    __shared__ float As[2][16][132];
    __shared__ float Bs[2][16][64];

    int tid = threadIdx.x;
    int bm = blockIdx.y * 128, bn = blockIdx.x * 64;
    int ty = tid >> 4, tx = tid & 15;
    int z = blockIdx.z;

    const float* B    = (z == 0) ? Wq : (z == 1) ? Wk : Wv;
    const float* bias = (z == 0) ? bq : (z == 1) ? bk : bv;
    float* C          = (z == 0) ? g_qp : (z == 1) ? g_kp : g_vp;
    bool relu = (z == 2);

    ull accA[4][2], accB[4][2];
    gemm_core(g_h, B, bm, bn, tid, As, Bs, accA, accB);

    int colg = bn + tx * 4;
    float4 bi = *reinterpret_cast<const float4*>(bias + colg);
    #pragma unroll
    for (int p = 0; p < 4; p++) {
        float lo[4], hi[4];
        unswap_rows(accA[p], accB[p], lo, hi);
        #pragma unroll
        for (int half = 0; half < 2; half++) {
            float* vv = half ? hi : lo;
            int row = bm + ty * 8 + p * 2 + half;
            float4 v;
            v.x = vv[0] + bi.x; v.y = vv[1] + bi.y;
            v.z = vv[2] + bi.z; v.w = vv[3] + bi.w;
            if (relu) {
                v.x = fmaxf(v.x, 0.0f); v.y = fmaxf(v.y, 0.0f);
                v.z = fmaxf(v.z, 0.0f); v.w = fmaxf(v.w, 0.0f);
            }
            *reinterpret_cast<float4*>(C + (size_t)row * 1024 + colg) = v;
        }
    }
}

// ======================= output projection GEMM (bias + residual) =======================
// grid 512 @ 4 CTAs/SM -> 592 slots: SINGLE WAVE (was 1.15 waves @ 3/SM).
__global__ __launch_bounds__(256, 4) void out_gemm(const float* __restrict__ Wo,
                                                const float* __restrict__ bo,
                                                const float* __restrict__ R,
                                                float* __restrict__ C) {
    __shared__ float As[2][16][132];
    __shared__ float Bs[2][16][64];

    int tid = threadIdx.x;
    int bm = blockIdx.y * 128, bn = blockIdx.x * 64;
    int ty = tid >> 4, tx = tid & 15;

    ull accA[4][2], accB[4][2];
    gemm_core(g_o, Wo, bm, bn, tid, As, Bs, accA, accB);

    int colg = bn + tx * 4;
    float4 bi = *reinterpret_cast<const float4*>(bo + colg);
    #pragma unroll
    for (int p = 0; p < 4; p++) {
        float lo[4], hi[4];
        unswap_rows(accA[p], accB[p], lo, hi);
        #pragma unroll
        for (int half = 0; half < 2; half++) {
            float* vv = half ? hi : lo;
            int row = bm + ty * 8 + p * 2 + half;
            float4 r4 = *reinterpret_cast<const float4*>(R + (size_t)row * 1024 + colg);
            float4 v;
            v.x = vv[0] + bi.x + r4.x; v.y = vv[1] + bi.y + r4.y;
            v.z = vv[2] + bi.z + r4.z; v.w = vv[3] + bi.w + r4.w;
            *reinterpret_cast<float4*>(C + (size_t)row * 1024 + colg) = v;
        }
    }
}

// ======================= Flash attention (fp32, FFMA2, single-buffer K/V, 3 CTAs/SM) =====
// Single-buffered K/V with register prefetch (3 syncs/tile) cuts smem to 69.6KB ->
// 3 CTAs/SM (24 warps) instead of 2; K-prefetch regs live only over the S loop,
// V-prefetch regs only over the PV loop (fits the 84-reg cap of launch_bounds(256,3)).
// No-max streaming softmax (scores O(1); fminf clamp guarantees finiteness).
// thread (ty,tx): q-rows ty*4..+3 (2 pairs), cols tx*4..+3; mixed-label accumulators
// A[p][q]=(r0c0,r1c1), B[p][q]=(r0c1,r1c0).
#define PADW 68
#define TILE_F (64 * PADW)
#define ATTN_SMEM (4 * TILE_F * 4)   // 69632 B -> 3 CTAs/SM
#define SCORE_CLAMP 60.0f

__global__ __launch_bounds__(256, 3) void attn_kernel() {
    extern __shared__ float sm[];
    float* Qt  = sm;
    float* Kt  = sm + 1 * TILE_F;
    float* Vsm = sm + 2 * TILE_F;
    float* Pt  = sm + 3 * TILE_F;

    int tid = threadIdx.x;
    int ty = tid >> 4, tx = tid & 15;
    int bh = blockIdx.y;
    int b = bh >> 4, h = bh & 15;
    int q0 = blockIdx.x * 64;

    const float* Qg = g_qp + (size_t)b * N_TOK * D_MODEL + h * DH;
    const float* Kg = g_kp + (size_t)b * N_TOK * D_MODEL + h * DH;
    const float* Vg = g_vp + (size_t)b * N_TOK * D_MODEL + h * DH;

    int lr[4], ldg_[4];
    #pragma unroll
    for (int l = 0; l < 4; l++) {
        int idx = tid + l * 256;          // 0..1023
        lr[l] = idx >> 4;
        ldg_[l] = (idx & 15) << 2;
    }

    // prologue: Q transposed (pre-scaled) + K/V tile 0
    #pragma unroll
    for (int l = 0; l < 4; l++) {
        int r = lr[l], dg = ldg_[l];
        float4 q4 = *reinterpret_cast<const float4*>(Qg + (size_t)(q0 + r) * D_MODEL + dg);
        Qt[(dg + 0) * PADW + r] = q4.x * INV_TEMPER;
        Qt[(dg + 1) * PADW + r] = q4.y * INV_TEMPER;
        Qt[(dg + 2) * PADW + r] = q4.z * INV_TEMPER;
        Qt[(dg + 3) * PADW + r] = q4.w * INV_TEMPER;
        float4 k4 = *reinterpret_cast<const float4*>(Kg + (size_t)r * D_MODEL + dg);
        Kt[(dg + 0) * PADW + r] = k4.x;
        Kt[(dg + 1) * PADW + r] = k4.y;
        Kt[(dg + 2) * PADW + r] = k4.z;
        Kt[(dg + 3) * PADW + r] = k4.w;
        float4 v4 = *reinterpret_cast<const float4*>(Vg + (size_t)r * D_MODEL + dg);
        *reinterpret_cast<float4*>(&Vsm[r * PADW + dg]) = v4;
    }
    __syncthreads();

    float lsum[4];
    ull oA[2][2], oB[2][2];
    #pragma unroll
    for (int i = 0; i < 4; i++) lsum[i] = 0.0f;
    #pragma unroll
    for (int p = 0; p < 2; p++)
        #pragma unroll
        for (int q = 0; q < 2; q++) { oA[p][q] = 0ull; oB[p][q] = 0ull; }

    for (int kt = 0; kt < N_TOK; kt += 64) {
        bool has_next = (kt + 64) < N_TOK;

        // prefetch next K tile into regs (latency hidden by the S loop)
        float4 kreg[4];
        if (has_next) {
            #pragma unroll
            for (int l = 0; l < 4; l++)
                kreg[l] = *reinterpret_cast<const float4*>(
                    Kg + (size_t)(kt + 64 + lr[l]) * D_MODEL + ldg_[l]);
        }

        // ---- S = Q.K^T, swapped-pair FFMA2 ----
        ull sA[2][2], sB[2][2];
        #pragma unroll
        for (int p = 0; p < 2; p++)
            #pragma unroll
            for (int q = 0; q < 2; q++) { sA[p][q] = 0ull; sB[p][q] = 0ull; }

        for (int d = 0; d < 64; d++) {
            float4 qf = *reinterpret_cast<const float4*>(&Qt[d * PADW + ty * 4]);
            ull a01 = rp2(qf.x);
            ull a23 = rp2(qf.z);
            float4 b4 = *reinterpret_cast<float4*>(&Kt[d * PADW + tx * 4]);
            ull b01 = rp2(b4.x), b23 = rp2(b4.z);               // direct: zero-MOV
            ull b10 = pk2(b4.y, b4.x), b32 = pk2(b4.w, b4.z);   // swapped
            sA[0][0] = fma2(a01, b01, sA[0][0]);
            sB[0][0] = fma2(a01, b10, sB[0][0]);
            sA[0][1] = fma2(a01, b23, sA[0][1]);
            sB[0][1] = fma2(a01, b32, sB[0][1]);
            sA[1][0] = fma2(a23, b01, sA[1][0]);
            sB[1][0] = fma2(a23, b10, sB[1][0]);
            sA[1][1] = fma2(a23, b23, sA[1][1]);
            sB[1][1] = fma2(a23, b32, sB[1][1]);
        }

        // ---- unswap labels; streaming softmax numerator p = exp(clamp(s)) ----
        float s[4][4];
        #pragma unroll
        for (int p = 0; p < 2; p++)
            #pragma unroll
            for (int q = 0; q < 2; q++) {
                float al, ah, bl, bhh;
                upk2(al, ah, sA[p][q]);   // (r0cq0, r1cq1)
                upk2(bl, bhh, sB[p][q]);  // (r0cq1, r1cq0)
                s[2 * p + 0][2 * q + 0] = al;
                s[2 * p + 1][2 * q + 1] = ah;
                s[2 * p + 0][2 * q + 1] = bl;
                s[2 * p + 1][2 * q + 0] = bhh;
            }
        #pragma unroll
        for (int i = 0; i < 4; i++) {
            float p0 = __expf(fminf(s[i][0], SCORE_CLAMP));
            float p1 = __expf(fminf(s[i][1], SCORE_CLAMP));
            float p2 = __expf(fminf(s[i][2], SCORE_CLAMP));
            float p3 = __expf(fminf(s[i][3], SCORE_CLAMP));
            float rsum = p0 + p1 + p2 + p3;
            #pragma unroll
            for (int o = 8; o > 0; o >>= 1)
                rsum += __shfl_xor_sync(0xffffffffu, rsum, o);
            lsum[i] += rsum;
            s[i][0] = p0; s[i][1] = p1; s[i][2] = p2; s[i][3] = p3;
        }
        // write P transposed ([kcol][qrow]) as row pairs
        #pragma unroll
        for (int j = 0; j < 4; j++) {
            *reinterpret_cast<ull*>(&Pt[(tx * 4 + j) * PADW + ty * 4]) = pk2(s[0][j], s[1][j]);
            *reinterpret_cast<ull*>(&Pt[(tx * 4 + j) * PADW + ty * 4 + 2]) = pk2(s[2][j], s[3][j]);
        }
        __syncthreads();   // (1) Pt visible; all S-reads of Kt complete

        // store prefetched K over Kt (no Kt readers until after sync (3));
        // then prefetch next V into regs (latency hidden by the PV loop)
        float4 vreg[4];
        if (has_next) {
            #pragma unroll
            for (int l = 0; l < 4; l++) {
                int r = lr[l], dg = ldg_[l];
                Kt[(dg + 0) * PADW + r] = kreg[l].x;
                Kt[(dg + 1) * PADW + r] = kreg[l].y;
                Kt[(dg + 2) * PADW + r] = kreg[l].z;
                Kt[(dg + 3) * PADW + r] = kreg[l].w;
                vreg[l] = *reinterpret_cast<const float4*>(
                    Vg + (size_t)(kt + 64 + lr[l]) * D_MODEL + ldg_[l]);
            }
        }

        // ---- O += P.V, swapped-pair FFMA2 (no rescale: no running max) ----
        for (int k = 0; k < 64; k++) {
            float4 pf = *reinterpret_cast<const float4*>(&Pt[k * PADW + ty * 4]);
            ull a01 = rp2(pf.x);
            ull a23 = rp2(pf.z);
            float4 v4 = *reinterpret_cast<float4*>(&Vsm[k * PADW + tx * 4]);
            ull b01 = rp2(v4.x), b23 = rp2(v4.z);               // direct: zero-MOV
            ull b10 = pk2(v4.y, v4.x), b32 = pk2(v4.w, v4.z);   // swapped
            oA[0][0] = fma2(a01, b01, oA[0][0]);
            oB[0][0] = fma2(a01, b10, oB[0][0]);
            oA[0][1] = fma2(a01, b23, oA[0][1]);
            oB[0][1] = fma2(a01, b32, oB[0][1]);
            oA[1][0] = fma2(a23, b01, oA[1][0]);
            oB[1][0] = fma2(a23, b10, oB[1][0]);
            oA[1][1] = fma2(a23, b23, oA[1][1]);
            oB[1][1] = fma2(a23, b32, oB[1][1]);
        }
        __syncthreads();   // (2) PV reads of Vsm/Pt retired; Kt stores visible

        if (has_next) {
            #pragma unroll
            for (int l = 0; l < 4; l++)
                *reinterpret_cast<float4*>(&Vsm[lr[l] * PADW + ldg_[l]]) = vreg[l];
            __syncthreads();   // (3) Vsm (and Kt) visible for next tile
        }
    }

    // epilogue: unswap labels, normalize, write O as [b][h][t][d] (== merged view)
    float* Og = g_o + ((size_t)(b * NHEAD + h) * N_TOK) * DH;
    float o[4][4];
    #pragma unroll
    for (int p = 0; p < 2; p++)
        #pragma unroll
        for (int q = 0; q < 2; q++) {
            float al, ah, bl, bhh;
            upk2(al, ah, oA[p][q]);   // (r0cq0, r1cq1)
            upk2(bl, bhh, oB[p][q]);  // (r0cq1, r1cq0)
            o[2 * p + 0][2 * q + 0] = al;
            o[2 * p + 1][2 * q + 1] = ah;
            o[2 * p + 0][2 * q + 1] = bl;
            o[2 * p + 1][2 * q + 0] = bhh;
        }
    #pragma unroll
    for (int i = 0; i < 4; i++) {
        float inv = 1.0f / lsum[i];
        int row = q0 + ty * 4 + i;
        float4 w;
        w.x = o[i][0] * inv; w.y = o[i][1] * inv;
        w.z = o[i][2] * inv; w.w = o[i][3] * inv;
        *reinterpret_cast<float4*>(Og + (size_t)row * DH + tx * 4) = w;
    }
}

// ======================= launch =======================
extern "C" void kernel_launch(void* const* d_in, const int* in_sizes, int n_in,
                              void* d_out, int out_size) {
    const float* q     = (const float*)d_in[0];
    // d_in[1] (k) and d_in[2] (v) are ignored by the reference module.
    const float* gamma = (const float*)d_in[3];
    const float* beta  = (const float*)d_in[4];
    const float* Wq    = (const float*)d_in[5];
    const float* bq    = (const float*)d_in[6];
    const float* Wk    = (const float*)d_in[7];
    const float* bk    = (const float*)d_in[8];
    const float* Wv    = (const float*)d_in[9];
    const float* bv    = (const float*)d_in[10];
    const float* Wo    = (const float*)d_in[11];
    const float* bo    = (const float*)d_in[12];
    float* out = (float*)d_out;

    cudaFuncSetAttribute(attn_kernel,
                         cudaFuncAttributeMaxDynamicSharedMemorySize, ATTN_SMEM);

    ln_kernel<<<TOKENS, 256>>>(q, gamma, beta);

    dim3 qkv_grid(D_MODEL / 64, TOKENS / 128, 3);   // (16, 32, 3) - one launch
    qkv_gemm<<<qkv_grid, 256>>>(Wq, bq, Wk, bk, Wv, bv);

    dim3 attn_grid(N_TOK / 64, BSZ * NHEAD);        // (32, 32)
    attn_kernel<<<attn_grid, 256, ATTN_SMEM>>>();

    dim3 gemm_grid(D_MODEL / 64, TOKENS / 128);     // (16, 32)
    out_gemm<<<gemm_grid, 256>>>(Wo, bo, q, out);
}

// round 17
// speedup vs baseline: 1.1114x; 1.1114x over previous
#include <cuda_runtime.h>

#define D_MODEL 1024
#define N_TOK   2048
#define BSZ     2
#define TOKENS  (BSZ * N_TOK)      // 4096
#define NHEAD   16
#define DH      64
#define INV_TEMPER 0.125f          // 1/sqrt(64)

typedef unsigned long long ull;

// ---- packed f32x2 helpers (sm_103a FFMA2 path; ptxas won't auto-fuse) ----
__device__ __forceinline__ ull pk2(float lo, float hi) {
    ull r;
    asm("mov.b64 %0, {%1, %2};" : "=l"(r)
        : "r"(__float_as_uint(lo)), "r"(__float_as_uint(hi)));
    return r;
}
__device__ __forceinline__ void upk2(float& lo, float& hi, ull v) {
    unsigned int a, b;
    asm("mov.b64 {%0, %1}, %2;" : "=r"(a), "=r"(b) : "l"(v));
    lo = __uint_as_float(a); hi = __uint_as_float(b);
}
__device__ __forceinline__ ull fma2(ull a, ull b, ull c) {
    ull d;
    asm("fma.rn.f32x2 %0, %1, %2, %3;" : "=l"(d) : "l"(a), "l"(b), "l"(c));
    return d;
}
// direct register-pair reinterpret (zero-MOV: LDS.128 result is an aligned quad)
__device__ __forceinline__ ull rp2(const float& f) {
    return *reinterpret_cast<const ull*>(&f);
}

// -------- scratch (static device globals; no allocation allowed) --------
__device__ float g_h[TOKENS * D_MODEL];
__device__ float g_qp[TOKENS * D_MODEL];
__device__ float g_kp[TOKENS * D_MODEL];
__device__ float g_vp[TOKENS * D_MODEL];
__device__ float g_o[TOKENS * D_MODEL];

// ======================= LayerNorm =======================
__global__ __launch_bounds__(256) void ln_kernel(const float* __restrict__ x,
                          const float* __restrict__ gamma,
                          const float* __restrict__ beta) {
    int t = blockIdx.x;
    const float* row = x + (size_t)t * D_MODEL;
    float* out = g_h + (size_t)t * D_MODEL;
    int tid = threadIdx.x;

    float4 v = reinterpret_cast<const float4*>(row)[tid];
    float s  = v.x + v.y + v.z + v.w;
    float ss = v.x * v.x + v.y * v.y + v.z * v.z + v.w * v.w;

    #pragma unroll
    for (int o = 16; o > 0; o >>= 1) {
        s  += __shfl_xor_sync(0xffffffffu, s,  o);
        ss += __shfl_xor_sync(0xffffffffu, ss, o);
    }
    __shared__ float rs[8], rss[8];
    __shared__ float mu_s, rstd_s;
    int w = tid >> 5, l = tid & 31;
    if (l == 0) { rs[w] = s; rss[w] = ss; }
    __syncthreads();
    if (tid == 0) {
        float S = 0.f, SS = 0.f;
        #pragma unroll
        for (int i = 0; i < 8; i++) { S += rs[i]; SS += rss[i]; }
        float mu  = S * (1.0f / D_MODEL);
        float var = SS * (1.0f / D_MODEL) - mu * mu;
        mu_s = mu;
        rstd_s = rsqrtf(var + 1e-5f);
    }
    __syncthreads();
    float mu = mu_s, rstd = rstd_s;

    float4 g = reinterpret_cast<const float4*>(gamma)[tid];
    float4 b = reinterpret_cast<const float4*>(beta)[tid];
    float4 o;
    o.x = (v.x - mu) * rstd * g.x + b.x;
    o.y = (v.y - mu) * rstd * g.y + b.y;
    o.z = (v.z - mu) * rstd * g.z + b.z;
    o.w = (v.w - mu) * rstd * g.w + b.w;
    reinterpret_cast<float4*>(out)[tid] = o;
}

// ============ GEMM core: 128x128x16 tile, 8x8/thread, FFMA2 swapped-pair ============
// 1.0 B(LDS)/MAC (was 1.5): lifts the measured smem-BW ceiling (L1=70.5%, fma=48.8%).
// Thread (ty,tx): rows ty*8..+7 (4 pairs), cols {tx*4..+3} u {64+tx*4..+3} (4 col-pairs).
// accA[p][q] = (C[r0][cq0], C[r1][cq1]); accB[p][q] = (C[r0][cq1], C[r1][cq0]).
__device__ __forceinline__ void gemm_core(const float* __restrict__ A,
                                          const float* __restrict__ B,
                                          int bm, int bn, int tid,
                                          float As[2][16][132], float Bs[2][16][128],
                                          ull accA[4][4], ull accB[4][4]) {
    const int Kdim = 1024, Ndim = 1024;
    const int NKT = Kdim / 16;      // 64 k-tiles
    int ty = tid >> 4, tx = tid & 15;

    int ar = tid >> 1, acg = (tid & 1) << 3;           // A: row, col-group(8)
    int brr = tid >> 4, bcc = (tid & 15) << 2;         // B: row, col-group(4) x2 halves
    const float* Ap = A + (size_t)(bm + ar) * Kdim + acg;
    const float* Bp = B + (size_t)brr * Ndim + bn + bcc;

    #pragma unroll
    for (int p = 0; p < 4; p++)
        #pragma unroll
        for (int q = 0; q < 4; q++) { accA[p][q] = 0ull; accB[p][q] = 0ull; }

    // prologue: k-tile 0 -> buffer 0
    {
        float4 a0 = *reinterpret_cast<const float4*>(Ap);
        float4 a1 = *reinterpret_cast<const float4*>(Ap + 4);
        As[0][acg + 0][ar] = a0.x; As[0][acg + 1][ar] = a0.y;
        As[0][acg + 2][ar] = a0.z; As[0][acg + 3][ar] = a0.w;
        As[0][acg + 4][ar] = a1.x; As[0][acg + 5][ar] = a1.y;
        As[0][acg + 6][ar] = a1.z; As[0][acg + 7][ar] = a1.w;
        float4 b0 = *reinterpret_cast<const float4*>(Bp);
        float4 b1 = *reinterpret_cast<const float4*>(Bp + 64);
        *reinterpret_cast<float4*>(&Bs[0][brr][bcc]) = b0;
        *reinterpret_cast<float4*>(&Bs[0][brr][bcc + 64]) = b1;
    }
    Ap += 16;
    Bp += 16 * Ndim;
    __syncthreads();

    for (int kt = 0; kt < NKT; kt++) {
        int cur = kt & 1;
        float4 pa0, pa1, pb0, pb1;
        if (kt < NKT - 1) {
            pa0 = *reinterpret_cast<const float4*>(Ap);
            pa1 = *reinterpret_cast<const float4*>(Ap + 4);
            pb0 = *reinterpret_cast<const float4*>(Bp);
            pb1 = *reinterpret_cast<const float4*>(Bp + 64);
            Ap += 16;
            Bp += 16 * Ndim;
        }
        #pragma unroll
        for (int kk = 0; kk < 16; kk++) {
            float4 af0 = *reinterpret_cast<const float4*>(&As[cur][kk][ty * 8]);
            float4 af1 = *reinterpret_cast<const float4*>(&As[cur][kk][ty * 8 + 4]);
            ull a[4];
            a[0] = rp2(af0.x);
            a[1] = rp2(af0.z);
            a[2] = rp2(af1.x);
            a[3] = rp2(af1.z);
            float4 bf0 = *reinterpret_cast<float4*>(&Bs[cur][kk][tx * 4]);
            float4 bf1 = *reinterpret_cast<float4*>(&Bs[cur][kk][64 + tx * 4]);
            ull b01 = rp2(bf0.x), b23 = rp2(bf0.z);             // direct: zero-MOV
            ull b45 = rp2(bf1.x), b67 = rp2(bf1.z);
            ull b10 = pk2(bf0.y, bf0.x), b32 = pk2(bf0.w, bf0.z);
            ull b54 = pk2(bf1.y, bf1.x), b76 = pk2(bf1.w, bf1.z);
            #pragma unroll
            for (int p = 0; p < 4; p++) {
                accA[p][0] = fma2(a[p], b01, accA[p][0]);
                accB[p][0] = fma2(a[p], b10, accB[p][0]);
                accA[p][1] = fma2(a[p], b23, accA[p][1]);
                accB[p][1] = fma2(a[p], b32, accB[p][1]);
                accA[p][2] = fma2(a[p], b45, accA[p][2]);
                accB[p][2] = fma2(a[p], b54, accB[p][2]);
                accA[p][3] = fma2(a[p], b67, accA[p][3]);
                accB[p][3] = fma2(a[p], b76, accB[p][3]);
            }
        }
        if (kt < NKT - 1) {
            int nxt = cur ^ 1;
            As[nxt][acg + 0][ar] = pa0.x; As[nxt][acg + 1][ar] = pa0.y;
            As[nxt][acg + 2][ar] = pa0.z; As[nxt][acg + 3][ar] = pa0.w;
            As[nxt][acg + 4][ar] = pa1.x; As[nxt][acg + 5][ar] = pa1.y;
            As[nxt][acg + 6][ar] = pa1.z; As[nxt][acg + 7][ar] = pa1.w;
            *reinterpret_cast<float4*>(&Bs[nxt][brr][bcc]) = pb0;
            *reinterpret_cast<float4*>(&Bs[nxt][brr][bcc + 64]) = pb1;
        }
        __syncthreads();
    }
}

// unpack mixed-label accumulators of one row-pair / one 4-col group
__device__ __forceinline__ void unswap_rows(const ull* accA, const ull* accB,
                                            float lo[4], float hi[4]) {
    float a0l, a0h, b0l, b0h, a1l, a1h, b1l, b1h;
    upk2(a0l, a0h, accA[0]);   // (r0c0, r1c1)
    upk2(b0l, b0h, accB[0]);   // (r0c1, r1c0)
    upk2(a1l, a1h, accA[1]);   // (r0c2, r1c3)
    upk2(b1l, b1h, accB[1]);   // (r0c3, r1c2)
    lo[0] = a0l; lo[1] = b0l; lo[2] = a1l; lo[3] = b1l;   // row r0
    hi[0] = b0h; hi[1] = a0h; hi[2] = b1h; hi[3] = a1h;   // row r1
}

// ======================= fused Q/K/V projection GEMM (one launch, 3 outputs) ============
__global__ __launch_bounds__(256, 2) void qkv_gemm(const float* __restrict__ Wq,
                                                const float* __restrict__ bq,
                                                const float* __restrict__ Wk,
                                                const float* __restrict__ bk,
                                                const float* __restrict__ Wv,
                                                const float* __restrict__ bv) {
    __shared__ float As[2][16][132];
    __shared__ float Bs[2][16][128];

    int tid = threadIdx.x;
    int bm = blockIdx.y * 128, bn = blockIdx.x * 128;
    int ty = tid >> 4, tx = tid & 15;
    int z = blockIdx.z;

    const float* B    = (z == 0) ? Wq : (z == 1) ? Wk : Wv;
    const float* bias = (z == 0) ? bq : (z == 1) ? bk : bv;
    float* C          = (z == 0) ? g_qp : (z == 1) ? g_kp : g_vp;
    bool relu = (z == 2);

    ull accA[4][4], accB[4][4];
    gemm_core(g_h, B, bm, bn, tid, As, Bs, accA, accB);

    int colg = bn + tx * 4;
    float4 bi0 = *reinterpret_cast<const float4*>(bias + colg);
    float4 bi1 = *reinterpret_cast<const float4*>(bias + colg + 64);
    #pragma unroll
    for (int p = 0; p < 4; p++) {
        #pragma unroll
        for (int g = 0; g < 2; g++) {
            float lo[4], hi[4];
            unswap_rows(&accA[p][2 * g], &accB[p][2 * g], lo, hi);
            float4 bi = g ? bi1 : bi0;
            int cg = colg + g * 64;
            #pragma unroll
            for (int half = 0; half < 2; half++) {
                float* vv = half ? hi : lo;
                int row = bm + ty * 8 + p * 2 + half;
                float4 v;
                v.x = vv[0] + bi.x; v.y = vv[1] + bi.y;
                v.z = vv[2] + bi.z; v.w = vv[3] + bi.w;
                if (relu) {
                    v.x = fmaxf(v.x, 0.0f); v.y = fmaxf(v.y, 0.0f);
                    v.z = fmaxf(v.z, 0.0f); v.w = fmaxf(v.w, 0.0f);
                }
                *reinterpret_cast<float4*>(C + (size_t)row * 1024 + cg) = v;
            }
        }
    }
}

// ======================= output projection GEMM (bias + residual) =======================
// grid 256 CTAs @ 2 CTAs/SM (296 slots): single wave.
__global__ __launch_bounds__(256, 2) void out_gemm(const float* __restrict__ Wo,
                                                const float* __restrict__ bo,
                                                const float* __restrict__ R,
                                                float* __restrict__ C) {
    __shared__ float As[2][16][132];
    __shared__ float Bs[2][16][128];

    int tid = threadIdx.x;
    int bm = blockIdx.y * 128, bn = blockIdx.x * 128;
    int ty = tid >> 4, tx = tid & 15;

    ull accA[4][4], accB[4][4];
    gemm_core(g_o, Wo, bm, bn, tid, As, Bs, accA, accB);

    int colg = bn + tx * 4;
    float4 bi0 = *reinterpret_cast<const float4*>(bo + colg);
    float4 bi1 = *reinterpret_cast<const float4*>(bo + colg + 64);
    #pragma unroll
    for (int p = 0; p < 4; p++) {
        #pragma unroll
        for (int g = 0; g < 2; g++) {
            float lo[4], hi[4];
            unswap_rows(&accA[p][2 * g], &accB[p][2 * g], lo, hi);
            float4 bi = g ? bi1 : bi0;
            int cg = colg + g * 64;
            #pragma unroll
            for (int half = 0; half < 2; half++) {
                float* vv = half ? hi : lo;
                int row = bm + ty * 8 + p * 2 + half;
                float4 r4 = *reinterpret_cast<const float4*>(R + (size_t)row * 1024 + cg);
                float4 v;
                v.x = vv[0] + bi.x + r4.x; v.y = vv[1] + bi.y + r4.y;
                v.z = vv[2] + bi.z + r4.z; v.w = vv[3] + bi.w + r4.w;
                *reinterpret_cast<float4*>(C + (size_t)row * 1024 + cg) = v;
            }
        }
    }
}

// ======================= Flash attention (fp32, FFMA2, single-buffer K/V, 3 CTAs/SM) =====
// (unchanged from R13 measured config)
#define PADW 68
#define TILE_F (64 * PADW)
#define ATTN_SMEM (4 * TILE_F * 4)   // 69632 B -> 3 CTAs/SM
#define SCORE_CLAMP 60.0f

__global__ __launch_bounds__(256, 3) void attn_kernel() {
    extern __shared__ float sm[];
    float* Qt  = sm;
    float* Kt  = sm + 1 * TILE_F;
    float* Vsm = sm + 2 * TILE_F;
    float* Pt  = sm + 3 * TILE_F;

    int tid = threadIdx.x;
    int ty = tid >> 4, tx = tid & 15;
    int bh = blockIdx.y;
    int b = bh >> 4, h = bh & 15;
    int q0 = blockIdx.x * 64;

    const float* Qg = g_qp + (size_t)b * N_TOK * D_MODEL + h * DH;
    const float* Kg = g_kp + (size_t)b * N_TOK * D_MODEL + h * DH;
    const float* Vg = g_vp + (size_t)b * N_TOK * D_MODEL + h * DH;

    int lr[4], ldg_[4];
    #pragma unroll
    for (int l = 0; l < 4; l++) {
        int idx = tid + l * 256;          // 0..1023
        lr[l] = idx >> 4;
        ldg_[l] = (idx & 15) << 2;
    }

    // prologue: Q transposed (pre-scaled) + K/V tile 0
    #pragma unroll
    for (int l = 0; l < 4; l++) {
        int r = lr[l], dg = ldg_[l];
        float4 q4 = *reinterpret_cast<const float4*>(Qg + (size_t)(q0 + r) * D_MODEL + dg);
        Qt[(dg + 0) * PADW + r] = q4.x * INV_TEMPER;
        Qt[(dg + 1) * PADW + r] = q4.y * INV_TEMPER;
        Qt[(dg + 2) * PADW + r] = q4.z * INV_TEMPER;
        Qt[(dg + 3) * PADW + r] = q4.w * INV_TEMPER;
        float4 k4 = *reinterpret_cast<const float4*>(Kg + (size_t)r * D_MODEL + dg);
        Kt[(dg + 0) * PADW + r] = k4.x;
        Kt[(dg + 1) * PADW + r] = k4.y;
        Kt[(dg + 2) * PADW + r] = k4.z;
        Kt[(dg + 3) * PADW + r] = k4.w;
        float4 v4 = *reinterpret_cast<const float4*>(Vg + (size_t)r * D_MODEL + dg);
        *reinterpret_cast<float4*>(&Vsm[r * PADW + dg]) = v4;
    }
    __syncthreads();

    float lsum[4];
    ull oA[2][2], oB[2][2];
    #pragma unroll
    for (int i = 0; i < 4; i++) lsum[i] = 0.0f;
    #pragma unroll
    for (int p = 0; p < 2; p++)
        #pragma unroll
        for (int q = 0; q < 2; q++) { oA[p][q] = 0ull; oB[p][q] = 0ull; }

    for (int kt = 0; kt < N_TOK; kt += 64) {
        bool has_next = (kt + 64) < N_TOK;

        // prefetch next K tile into regs (latency hidden by the S loop)
        float4 kreg[4];
        if (has_next) {
            #pragma unroll
            for (int l = 0; l < 4; l++)
                kreg[l] = *reinterpret_cast<const float4*>(
                    Kg + (size_t)(kt + 64 + lr[l]) * D_MODEL + ldg_[l]);
        }

        // ---- S = Q.K^T, swapped-pair FFMA2 ----
        ull sA[2][2], sB[2][2];
        #pragma unroll
        for (int p = 0; p < 2; p++)
            #pragma unroll
            for (int q = 0; q < 2; q++) { sA[p][q] = 0ull; sB[p][q] = 0ull; }

        for (int d = 0; d < 64; d++) {
            float4 qf = *reinterpret_cast<const float4*>(&Qt[d * PADW + ty * 4]);
            ull a01 = rp2(qf.x);
            ull a23 = rp2(qf.z);
            float4 b4 = *reinterpret_cast<float4*>(&Kt[d * PADW + tx * 4]);
            ull b01 = rp2(b4.x), b23 = rp2(b4.z);               // direct: zero-MOV
            ull b10 = pk2(b4.y, b4.x), b32 = pk2(b4.w, b4.z);   // swapped
            sA[0][0] = fma2(a01, b01, sA[0][0]);
            sB[0][0] = fma2(a01, b10, sB[0][0]);
            sA[0][1] = fma2(a01, b23, sA[0][1]);
            sB[0][1] = fma2(a01, b32, sB[0][1]);
            sA[1][0] = fma2(a23, b01, sA[1][0]);
            sB[1][0] = fma2(a23, b10, sB[1][0]);
            sA[1][1] = fma2(a23, b23, sA[1][1]);
            sB[1][1] = fma2(a23, b32, sB[1][1]);
        }

        // ---- unswap labels; streaming softmax numerator p = exp(clamp(s)) ----
        float s[4][4];
        #pragma unroll
        for (int p = 0; p < 2; p++)
            #pragma unroll
            for (int q = 0; q < 2; q++) {
                float al, ah, bl, bhh;
                upk2(al, ah, sA[p][q]);   // (r0cq0, r1cq1)
                upk2(bl, bhh, sB[p][q]);  // (r0cq1, r1cq0)
                s[2 * p + 0][2 * q + 0] = al;
                s[2 * p + 1][2 * q + 1] = ah;
                s[2 * p + 0][2 * q + 1] = bl;
                s[2 * p + 1][2 * q + 0] = bhh;
            }
        #pragma unroll
        for (int i = 0; i < 4; i++) {
            float p0 = __expf(fminf(s[i][0], SCORE_CLAMP));
            float p1 = __expf(fminf(s[i][1], SCORE_CLAMP));
            float p2 = __expf(fminf(s[i][2], SCORE_CLAMP));
            float p3 = __expf(fminf(s[i][3], SCORE_CLAMP));
            float rsum = p0 + p1 + p2 + p3;
            #pragma unroll
            for (int o = 8; o > 0; o >>= 1)
                rsum += __shfl_xor_sync(0xffffffffu, rsum, o);
            lsum[i] += rsum;
            s[i][0] = p0; s[i][1] = p1; s[i][2] = p2; s[i][3] = p3;
        }
        // write P transposed ([kcol][qrow]) as row pairs
        #pragma unroll
        for (int j = 0; j < 4; j++) {
            *reinterpret_cast<ull*>(&Pt[(tx * 4 + j) * PADW + ty * 4]) = pk2(s[0][j], s[1][j]);
            *reinterpret_cast<ull*>(&Pt[(tx * 4 + j) * PADW + ty * 4 + 2]) = pk2(s[2][j], s[3][j]);
        }
        __syncthreads();   // (1) Pt visible; all S-reads of Kt complete

        // store prefetched K over Kt (no Kt readers until after sync (3));
        // then prefetch next V into regs (latency hidden by the PV loop)
        float4 vreg[4];
        if (has_next) {
            #pragma unroll
            for (int l = 0; l < 4; l++) {
                int r = lr[l], dg = ldg_[l];
                Kt[(dg + 0) * PADW + r] = kreg[l].x;
                Kt[(dg + 1) * PADW + r] = kreg[l].y;
                Kt[(dg + 2) * PADW + r] = kreg[l].z;
                Kt[(dg + 3) * PADW + r] = kreg[l].w;
                vreg[l] = *reinterpret_cast<const float4*>(
                    Vg + (size_t)(kt + 64 + lr[l]) * D_MODEL + ldg_[l]);
            }
        }

        // ---- O += P.V, swapped-pair FFMA2 (no rescale: no running max) ----
        for (int k = 0; k < 64; k++) {
            float4 pf = *reinterpret_cast<const float4*>(&Pt[k * PADW + ty * 4]);
            ull a01 = rp2(pf.x);
            ull a23 = rp2(pf.z);
            float4 v4 = *reinterpret_cast<float4*>(&Vsm[k * PADW + tx * 4]);
            ull b01 = rp2(v4.x), b23 = rp2(v4.z);               // direct: zero-MOV
            ull b10 = pk2(v4.y, v4.x), b32 = pk2(v4.w, v4.z);   // swapped
            oA[0][0] = fma2(a01, b01, oA[0][0]);
            oB[0][0] = fma2(a01, b10, oB[0][0]);
            oA[0][1] = fma2(a01, b23, oA[0][1]);
            oB[0][1] = fma2(a01, b32, oB[0][1]);
            oA[1][0] = fma2(a23, b01, oA[1][0]);
            oB[1][0] = fma2(a23, b10, oB[1][0]);
            oA[1][1] = fma2(a23, b23, oA[1][1]);
            oB[1][1] = fma2(a23, b32, oB[1][1]);
        }
        __syncthreads();   // (2) PV reads of Vsm/Pt retired; Kt stores visible

        if (has_next) {
            #pragma unroll
            for (int l = 0; l < 4; l++)
                *reinterpret_cast<float4*>(&Vsm[lr[l] * PADW + ldg_[l]]) = vreg[l];
            __syncthreads();   // (3) Vsm (and Kt) visible for next tile
        }
    }

    // epilogue: unswap labels, normalize, write O as [b][h][t][d] (== merged view)
    float* Og = g_o + ((size_t)(b * NHEAD + h) * N_TOK) * DH;
    float o[4][4];
    #pragma unroll
    for (int p = 0; p < 2; p++)
        #pragma unroll
        for (int q = 0; q < 2; q++) {
            float al, ah, bl, bhh;
            upk2(al, ah, oA[p][q]);   // (r0cq0, r1cq1)
            upk2(bl, bhh, oB[p][q]);  // (r0cq1, r1cq0)
            o[2 * p + 0][2 * q + 0] = al;
            o[2 * p + 1][2 * q + 1] = ah;
            o[2 * p + 0][2 * q + 1] = bl;
            o[2 * p + 1][2 * q + 0] = bhh;
        }
    #pragma unroll
    for (int i = 0; i < 4; i++) {
        float inv = 1.0f / lsum[i];
        int row = q0 + ty * 4 + i;
        float4 w;
        w.x = o[i][0] * inv; w.y = o[i][1] * inv;
        w.z = o[i][2] * inv; w.w = o[i][3] * inv;
        *reinterpret_cast<float4*>(Og + (size_t)row * DH + tx * 4) = w;
    }
}

// ======================= launch =======================
extern "C" void kernel_launch(void* const* d_in, const int* in_sizes, int n_in,
                              void* d_out, int out_size) {
    const float* q     = (const float*)d_in[0];
    // d_in[1] (k) and d_in[2] (v) are ignored by the reference module.
    const float* gamma = (const float*)d_in[3];
    const float* beta  = (const float*)d_in[4];
    const float* Wq    = (const float*)d_in[5];
    const float* bq    = (const float*)d_in[6];
    const float* Wk    = (const float*)d_in[7];
    const float* bk    = (const float*)d_in[8];
    const float* Wv    = (const float*)d_in[9];
    const float* bv    = (const float*)d_in[10];
    const float* Wo    = (const float*)d_in[11];
    const float* bo    = (const float*)d_in[12];
    float* out = (float*)d_out;

    cudaFuncSetAttribute(attn_kernel,
                         cudaFuncAttributeMaxDynamicSharedMemorySize, ATTN_SMEM);

    ln_kernel<<<TOKENS, 256>>>(q, gamma, beta);

    dim3 qkv_grid(D_MODEL / 128, TOKENS / 128, 3);   // (8, 32, 3) - one launch
    qkv_gemm<<<qkv_grid, 256>>>(Wq, bq, Wk, bk, Wv, bv);

    dim3 attn_grid(N_TOK / 64, BSZ * NHEAD);         // (32, 32)
    attn_kernel<<<attn_grid, 256, ATTN_SMEM>>>();

    dim3 gemm_grid(D_MODEL / 128, TOKENS / 128);     // (8, 32) = 256 CTAs
    out_gemm<<<gemm_grid, 256>>>(Wo, bo, q, out);
}